// round 15
// baseline (speedup 1.0000x reference)
#include <cuda_runtime.h>
#include <cuda_fp16.h>
#include <cstdint>

// ---------------- problem dims ----------------
#define NTOK 4096
#define EDIM 1024
#define CDIM 1024
#define HDIM 4096
#define VDIM 32000
#define LN_EPS 1e-5f

// ---- fp16 1-term GEMM tiling: BM128 BN128 BK32, 8 warps, warp 64x32, 2-stage, 2 CTA/SM ----
#define LDA 40
#define LDB 136
#define APB (128 * LDA * 2)          // 10240 B (A plane)
#define BPB (32 * LDB * 2)           // 8704 B  (B plane)
#define STG (APB + BPB)              // 18944 B per stage
#define GEMM_SMEM (2 * STG)          // 37888 B -> 2 CTA/SM

// ---------------- scratch ----------------
__device__ __half g_wbuf[206569472];              // fp16 weight planes
__device__ __half g_xcs[4096 * 2048];             // concat plane
__device__ __half g_h1s[4096 * 4096];
__device__ __half g_hs [4096 * 4096];
__device__ float g_gate[NTOK * 3072];             // [delta | f | i]
__device__ float g_ctx [NTOK * CDIM];
__device__ float g_gbias[3072];

// weight plane offsets in __half elements
#define O_W00 0ull
#define O_W01 8388608ull
#define O_W10 25165824ull
#define O_W11 33554432ull
#define O_G0  50331648ull
#define O_OW  75497472ull

// ---------------- helpers ----------------
__device__ __forceinline__ uint32_t smem_u32(const void* p) {
    return (uint32_t)__cvta_generic_to_shared(p);
}
__device__ __forceinline__ void cpa16(uint32_t dst, const void* src) {
    asm volatile("cp.async.cg.shared.global [%0], [%1], 16;" :: "r"(dst), "l"(src));
}
__device__ __forceinline__ void ldm4(uint32_t* r, uint32_t a) {
    asm volatile("ldmatrix.sync.aligned.m8n8.x4.shared.b16 {%0,%1,%2,%3}, [%4];"
                 : "=r"(r[0]), "=r"(r[1]), "=r"(r[2]), "=r"(r[3]) : "r"(a));
}
__device__ __forceinline__ void ldmT4(uint32_t* r, uint32_t a) {
    asm volatile("ldmatrix.sync.aligned.m8n8.x4.trans.shared.b16 {%0,%1,%2,%3}, [%4];"
                 : "=r"(r[0]), "=r"(r[1]), "=r"(r[2]), "=r"(r[3]) : "r"(a));
}
__device__ __forceinline__ void mma_f16(float* d, const uint32_t* a, const uint32_t* b) {
    asm volatile("mma.sync.aligned.m16n8k16.row.col.f32.f16.f16.f32 "
                 "{%0,%1,%2,%3}, {%4,%5,%6,%7}, {%8,%9}, {%0,%1,%2,%3};"
                 : "+f"(d[0]), "+f"(d[1]), "+f"(d[2]), "+f"(d[3])
                 : "r"(a[0]), "r"(a[1]), "r"(a[2]), "r"(a[3]), "r"(b[0]), "r"(b[1]));
}
__device__ __forceinline__ uint32_t cvth(float x, float y) {
    __half2 h = __floats2half2_rn(x, y);
    return *reinterpret_cast<uint32_t*>(&h);
}
template <int ACT>
__device__ __forceinline__ float actf(float x, int col) {
    if (ACT == 1) return fmaxf(x, 0.0f);
    if (ACT == 4) return (col < 1024) ? tanhf(x) : 1.0f / (1.0f + expf(-x));
    return x;
}

// ---------------- persistent 1-term GEMM: C[M,N] = act(fp16(A) @ fp16(B) + bias) ----------------
template <int ACT, int SPLIT_OUT>
__global__ void __launch_bounds__(256, 2)
hgemm(const __half* __restrict__ Ah,
      const __half* __restrict__ Bh,
      const float* __restrict__ bias,
      float* __restrict__ Cf, __half* __restrict__ Cs,
      int M, int N, int K, int tiles_m, int ntiles)
{
    extern __shared__ __align__(16) char smraw[];
    const uint32_t sb0 = smem_u32(smraw);

    const int t    = threadIdx.x;
    const int lane = t & 31;
    const int warp = t >> 5;
    const int wm   = warp >> 2;
    const int wn   = warp & 3;

    const int ar  = t >> 1;
    const int acH = (t & 1) * 16;
    const int br  = t >> 3;
    const int bcH = (t & 7) * 16;
    const uint32_t daB = (uint32_t)(ar * LDA + acH) * 2;
    const uint32_t dbB = (uint32_t)(br * LDB + bcH) * 2;
    const int nk = K / 32;

    for (int tile = blockIdx.x; tile < ntiles; tile += gridDim.x) {
        const int bm = (tile % tiles_m) * 128;
        const int bn = (tile / tiles_m) * 128;
        const __half* aS = Ah + (size_t)(bm + ar) * K + acH;
        const __half* bS = Bh + (size_t)br * N + bn + bcH;

        float acc[4][4][4];
#pragma unroll
        for (int a = 0; a < 4; a++)
#pragma unroll
            for (int b = 0; b < 4; b++)
#pragma unroll
                for (int c = 0; c < 4; c++) acc[a][b][c] = 0.0f;

#define ISSUE(s_)                                                       \
    do {                                                                \
        const int s__ = (s_);                                           \
        if (s__ < nk) {                                                 \
            const uint32_t st = sb0 + (uint32_t)(s__ & 1) * STG;        \
            const __half* pa = aS + s__ * 32;                           \
            const uint32_t da = st + daB;                               \
            cpa16(da, pa);            cpa16(da + 16, pa + 8);           \
            const __half* pb = bS + (size_t)(s__ * 32) * N;             \
            const uint32_t db = st + APB + dbB;                         \
            cpa16(db, pb);            cpa16(db + 16, pb + 8);           \
        }                                                               \
        asm volatile("cp.async.commit_group;" ::: "memory");            \
    } while (0)

        ISSUE(0); ISSUE(1);

        for (int it = 0; it < nk; ++it) {
            asm volatile("cp.async.wait_group 1;" ::: "memory");
            __syncthreads();

            const uint32_t st  = sb0 + (uint32_t)(it & 1) * STG;
            const uint32_t aHi = st;
            const uint32_t bPl = st + APB;

#pragma unroll
            for (int ks = 0; ks < 2; ++ks) {
                uint32_t fB[4][2];
                const int krow  = ks * 16 + (lane & 15);
                const int nbase = wn * 32 + ((lane >> 4) << 3);
#pragma unroll
                for (int g = 0; g < 2; ++g) {
                    const uint32_t off = (uint32_t)(krow * LDB + nbase + g * 16) * 2;
                    uint32_t r[4];
                    ldmT4(r, bPl + off);
                    fB[2 * g][0] = r[0]; fB[2 * g][1] = r[1];
                    fB[2 * g + 1][0] = r[2]; fB[2 * g + 1][1] = r[3];
                }
#pragma unroll
                for (int mt = 0; mt < 4; ++mt) {
                    uint32_t fH[4];
                    const uint32_t aoff =
                        (uint32_t)((wm * 64 + mt * 16 + (lane & 15)) * LDA +
                                   ks * 16 + ((lane >> 4) << 3)) * 2;
                    ldm4(fH, aHi + aoff);
#pragma unroll
                    for (int nt = 0; nt < 4; ++nt) mma_f16(acc[mt][nt], fH, fB[nt]);
                }
            }
            __syncthreads();
            ISSUE(it + 2);
        }
#undef ISSUE

        // ---- epilogue (registers + gmem only; next tile's ISSUE(0) is safe)
        const int rr = lane >> 2;
        const int cc = (lane & 3) * 2;
        if (SPLIT_OUT) {
            uint32_t* Chi = (uint32_t*)Cs;
#pragma unroll
            for (int mt = 0; mt < 4; ++mt) {
                const int row = bm + wm * 64 + mt * 16 + rr;
#pragma unroll
                for (int nt = 0; nt < 4; ++nt) {
                    const int col = bn + wn * 32 + nt * 8 + cc;
                    const float b0 = __ldg(bias + col);
                    const float b1 = __ldg(bias + col + 1);
                    Chi[((size_t)row * N + col) >> 1] =
                        cvth(actf<ACT>(acc[mt][nt][0] + b0, col),
                             actf<ACT>(acc[mt][nt][1] + b1, col));
                    Chi[((size_t)(row + 8) * N + col) >> 1] =
                        cvth(actf<ACT>(acc[mt][nt][2] + b0, col),
                             actf<ACT>(acc[mt][nt][3] + b1, col));
                }
            }
        } else {
#pragma unroll
            for (int mt = 0; mt < 4; ++mt) {
                const int row = bm + wm * 64 + mt * 16 + rr;
#pragma unroll
                for (int nt = 0; nt < 4; ++nt) {
                    const int col = bn + wn * 32 + nt * 8 + cc;
                    const float b0 = __ldg(bias + col);
                    const float b1 = __ldg(bias + col + 1);
                    float2 o0, o1;
                    o0.x = actf<ACT>(acc[mt][nt][0] + b0, col);
                    o0.y = actf<ACT>(acc[mt][nt][1] + b1, col);
                    o1.x = actf<ACT>(acc[mt][nt][2] + b0, col);
                    o1.y = actf<ACT>(acc[mt][nt][3] + b1, col);
                    *(float2*)(Cf + (size_t)row * N + col)       = o0;
                    *(float2*)(Cf + (size_t)(row + 8) * N + col) = o1;
                }
            }
        }
    }
}

// ---------------- weight convert fp32 -> fp16 plane ----------------
__device__ __forceinline__ void conv_one(
    long long i,
    const float* w00, const float* w01, const float* w10, const float* w11,
    const float* dw0, const float* fw0, const float* iw0,
    const float* ow, __half* wbuf)
{
    const float* s; long long jsrc; long long dsti = i;
    if (i < 4194304LL)        { s = w00; jsrc = i; }
    else if (i < 12582912LL)  { s = w01; jsrc = i - 4194304; }
    else if (i < 16777216LL)  { s = w10; jsrc = i - 12582912; }
    else if (i < 25165824LL)  { s = w11; jsrc = i - 16777216; }
    else if (i < 31457280LL) {
        const long long j = i - 25165824;
        const long long r = j / 1536, c2 = j % 1536;
        const int sel = (int)(c2 / 512);
        s = sel == 0 ? dw0 : (sel == 1 ? fw0 : iw0);
        jsrc = r * 512 + (c2 - (long long)sel * 512);
    }
    else { s = ow; jsrc = i - 31457280; dsti = i + 6291456; }  // skip unused G1 slot

    const float2 v = ((const float2*)s)[jsrc];
    ((uint32_t*)wbuf)[dsti] = cvth(v.x, v.y);
}

__global__ void __launch_bounds__(256)
wconv_range(const float* w00, const float* w01, const float* w10, const float* w11,
            const float* dw0, const float* fw0, const float* iw0,
            const float* ow, __half* wbuf, long long base, long long count)
{
    const long long i = base + (long long)blockIdx.x * 256 + threadIdx.x;
    if (i >= base + count || i >= 96993280LL) return;
    conv_one(i, w00, w01, w10, w11, dw0, fw0, iw0, ow, wbuf);
}

__global__ void __launch_bounds__(256)
gbias_kernel(const float* __restrict__ db, const float* __restrict__ fb,
             const float* __restrict__ ib, float* __restrict__ out)
{
    const int c = blockIdx.x * 256 + threadIdx.x;
    if (c >= 3072) return;
    out[c] = (c < 1024) ? db[c] : (c < 2048 ? fb[c - 1024] : ib[c - 2048]);
}

// ---------------- ctx half of concat -> fp16 plane (x half pre-filled by embed) ----------------
__global__ void __launch_bounds__(256)
concat_ctx_kernel(const float* __restrict__ ctx, __half* __restrict__ xcs, int first)
{
    const int gid = blockIdx.x * 256 + threadIdx.x;   // float4 over [4096,1024]
    const int row = gid >> 8;
    const int c4  = gid & 255;
    float4 v = first ? make_float4(0.f, 0.f, 0.f, 0.f)
                     : ((const float4*)ctx)[(size_t)row * 256 + c4];
    uint2* hi = (uint2*)xcs;
    hi[(size_t)row * 512 + 256 + c4] = make_uint2(cvth(v.x, v.y), cvth(v.z, v.w));
}

// ---------------- block reduction ----------------
__device__ __forceinline__ float block_sum(float v, float* sbuf) {
    const int lane = threadIdx.x & 31;
    const int wid  = threadIdx.x >> 5;
#pragma unroll
    for (int o = 16; o; o >>= 1) v += __shfl_xor_sync(0xffffffffu, v, o);
    if (lane == 0) sbuf[wid] = v;
    __syncthreads();
    if (threadIdx.x < 32) {
        float r = (threadIdx.x < 8) ? sbuf[threadIdx.x] : 0.0f;
#pragma unroll
        for (int o = 4; o; o >>= 1) r += __shfl_xor_sync(0xffffffffu, r, o);
        if (threadIdx.x == 0) sbuf[8] = r;
    }
    __syncthreads();
    return sbuf[8];
}

// ---------------- embed + LN -> x-half fp16 plane of xcs ----------------
__global__ void __launch_bounds__(256)
embed_ln_kernel(const int* __restrict__ ids, const float* __restrict__ table,
                const float* __restrict__ g, const float* __restrict__ b,
                __half* __restrict__ xcs)
{
    __shared__ float sbuf[16];
    const int row = blockIdx.x;
    const int t = threadIdx.x;
    const float4 v = ((const float4*)(table + (size_t)ids[row] * EDIM))[t];
    float s  = v.x + v.y + v.z + v.w;
    float s2 = v.x * v.x + v.y * v.y + v.z * v.z + v.w * v.w;
    const float S  = block_sum(s, sbuf);
    const float S2 = block_sum(s2, sbuf);
    const float mean = S * (1.0f / EDIM);
    const float var  = S2 * (1.0f / EDIM) - mean * mean;
    const float rs   = rsqrtf(var + LN_EPS);
    const int c0 = 4 * t;
    float4 o;
    o.x = (v.x - mean) * rs * g[c0]     + b[c0];
    o.y = (v.y - mean) * rs * g[c0 + 1] + b[c0 + 1];
    o.z = (v.z - mean) * rs * g[c0 + 2] + b[c0 + 2];
    o.w = (v.w - mean) * rs * g[c0 + 3] + b[c0 + 3];
    uint2* hi = (uint2*)xcs;
    hi[(size_t)row * 512 + t] = make_uint2(cvth(o.x, o.y), cvth(o.z, o.w));
}

// gates layout: [delta | f | i] per row of 3072
__global__ void __launch_bounds__(256)
gate_ln_kernel(const float* __restrict__ gates, float* __restrict__ ctx,
               const float* __restrict__ g, const float* __restrict__ b, int first)
{
    __shared__ float sbuf[16];
    const int row = blockIdx.x;
    const int t = threadIdx.x;
    const float* gr = gates + (size_t)row * 3072;
    float v[4];
    float s = 0.0f, s2 = 0.0f;
#pragma unroll
    for (int j = 0; j < 4; j++) {
        const int c = t + j * 256;
        const float cv = first ? 0.0f : ctx[(size_t)row * CDIM + c];
        v[j] = gr[1024 + c] * cv + gr[2048 + c] * gr[c];
        s += v[j]; s2 += v[j] * v[j];
    }
    const float S  = block_sum(s, sbuf);
    const float S2 = block_sum(s2, sbuf);
    const float mean = S * (1.0f / CDIM);
    const float var  = S2 * (1.0f / CDIM) - mean * mean;
    const float rs   = rsqrtf(var + LN_EPS);
#pragma unroll
    for (int j = 0; j < 4; j++) {
        const int c = t + j * 256;
        ctx[(size_t)row * CDIM + c] = (v[j] - mean) * rs * g[c] + b[c];
    }
}

// ---------------- host dispatch ----------------
static int g_num_ctas()
{
    int dev = 0, sms = 148;
    cudaGetDevice(&dev);
    cudaDeviceGetAttribute(&sms, cudaDevAttrMultiProcessorCount, dev);
    return sms * 2;
}

// mode 3: trunk relu, fp16 out | mode 1: gates tanh/sigm, fp32 out | mode 2: logits, fp32 out
static void run_gemm(int mode, const __half* Ah, const __half* Bh,
                     const float* bias, float* Cf, __half* Cs,
                     int M, int N, int K)
{
    const int tiles_m = M / 128;
    const int ntiles  = tiles_m * (N / 128);
    static int nctas = 0;
    if (nctas == 0) nctas = g_num_ctas();
    const int grid = ntiles < nctas ? ntiles : nctas;
    dim3 block(256);
    if (mode == 3) {
        cudaFuncSetAttribute(hgemm<1, 1>, cudaFuncAttributeMaxDynamicSharedMemorySize, GEMM_SMEM);
        hgemm<1, 1><<<grid, block, GEMM_SMEM>>>(Ah, Bh, bias, Cf, Cs, M, N, K, tiles_m, ntiles);
    } else if (mode == 1) {
        cudaFuncSetAttribute(hgemm<4, 0>, cudaFuncAttributeMaxDynamicSharedMemorySize, GEMM_SMEM);
        hgemm<4, 0><<<grid, block, GEMM_SMEM>>>(Ah, Bh, bias, Cf, Cs, M, N, K, tiles_m, ntiles);
    } else {
        cudaFuncSetAttribute(hgemm<0, 0>, cudaFuncAttributeMaxDynamicSharedMemorySize, GEMM_SMEM);
        hgemm<0, 0><<<grid, block, GEMM_SMEM>>>(Ah, Bh, bias, Cf, Cs, M, N, K, tiles_m, ntiles);
    }
}

extern "C" void kernel_launch(void* const* d_in, const int* in_sizes, int n_in,
                              void* d_out, int out_size)
{
    const int*   ids   = (const int*)d_in[0];
    const float* table = (const float*)d_in[1];
    const float* en_g  = (const float*)d_in[2];
    const float* en_b  = (const float*)d_in[3];
    const float* bA[2] = {(const float*)d_in[5],  (const float*)d_in[9]};
    const float* bB[2] = {(const float*)d_in[7],  (const float*)d_in[11]};
    const float* cg0   = (const float*)d_in[18];
    const float* cb0   = (const float*)d_in[19];
    const float* ob    = (const float*)d_in[29];
    float* out = (float*)d_out;

    __half *wbuf, *xcs, *h1s, *hs;
    float *gate, *ctx, *gbias;
    cudaGetSymbolAddress((void**)&wbuf,  g_wbuf);
    cudaGetSymbolAddress((void**)&xcs,   g_xcs);
    cudaGetSymbolAddress((void**)&h1s,   g_h1s);
    cudaGetSymbolAddress((void**)&hs,    g_hs);
    cudaGetSymbolAddress((void**)&gate,  g_gate);
    cudaGetSymbolAddress((void**)&ctx,   g_ctx);
    cudaGetSymbolAddress((void**)&gbias, g_gbias);

    const float* W[8] = {
        (const float*)d_in[4],  (const float*)d_in[6],
        (const float*)d_in[8],  (const float*)d_in[10],
        (const float*)d_in[12], (const float*)d_in[14], (const float*)d_in[16],
        (const float*)d_in[28]};

    // 0: embed(+x-half plane), 1: concat_ctx(blk0 zeros), 2: conv w00,
    // 3: trunk GEMM 1 (profiled), 4: conv rest, ...
    embed_ln_kernel<<<NTOK, 256>>>(ids, table, en_g, en_b, xcs);
    concat_ctx_kernel<<<(NTOK * 1024 / 4) / 256, 256>>>(ctx, xcs, 1);
    wconv_range<<<(4194304 + 255) / 256, 256>>>(
        W[0], W[1], W[2], W[3], W[4], W[5], W[6], W[7],
        wbuf, 0LL, 4194304LL);
    run_gemm(3, xcs, wbuf + O_W00, bA[0], nullptr, h1s, NTOK, HDIM, EDIM + CDIM);
    wconv_range<<<(int)((96993280LL - 4194304LL + 255) / 256), 256>>>(
        W[0], W[1], W[2], W[3], W[4], W[5], W[6], W[7],
        wbuf, 4194304LL, 96993280LL - 4194304LL);
    run_gemm(3, h1s, wbuf + O_W01, bB[0], nullptr, hs, NTOK, HDIM, HDIM);
    gbias_kernel<<<12, 256>>>((const float*)d_in[13], (const float*)d_in[15],
                              (const float*)d_in[17], gbias);
    run_gemm(1, hs, wbuf + O_G0, gbias, gate, nullptr, NTOK, 3072, HDIM);
    gate_ln_kernel<<<NTOK, 256>>>(gate, ctx, cg0, cb0, 1);

    // block 1 trunk (block-1 gates remain dead code: final ctx never read)
    concat_ctx_kernel<<<(NTOK * 1024 / 4) / 256, 256>>>(ctx, xcs, 0);
    run_gemm(3, xcs, wbuf + O_W10, bA[1], nullptr, h1s, NTOK, HDIM, EDIM + CDIM);
    run_gemm(3, h1s, wbuf + O_W11, bB[1], nullptr, hs,  NTOK, HDIM, HDIM);

    // logits
    run_gemm(2, hs, wbuf + O_OW, ob, out, nullptr, NTOK, VDIM, HDIM);
}

// round 16
// speedup vs baseline: 1.0445x; 1.0445x over previous
#include <cuda_runtime.h>
#include <cuda_fp16.h>
#include <cstdint>

// ---------------- problem dims ----------------
#define NTOK 4096
#define EDIM 1024
#define CDIM 1024
#define HDIM 4096
#define VDIM 32000
#define LN_EPS 1e-5f

// ---- fp16 1-term GEMM tiling: BM128 BN128 BK32, 8 warps, warp 64x32, 2-stage, 2 CTA/SM ----
#define LDA 40
#define LDB 136
#define APB (128 * LDA * 2)          // 10240 B (A plane)
#define BPB (32 * LDB * 2)           // 8704 B  (B plane)
#define STG (APB + BPB)              // 18944 B per stage
#define GEMM_SMEM (2 * STG)          // 37888 B -> 2 CTA/SM (regs cap occupancy)

// ---------------- scratch ----------------
__device__ __half g_wbuf[206569472];              // fp16 weight planes
__device__ __half g_xcs[4096 * 2048];             // concat plane
__device__ __half g_h1s[4096 * 4096];
__device__ __half g_hs [4096 * 4096];
__device__ float g_gate[NTOK * 3072];             // [delta | f | i]
__device__ float g_ctx [NTOK * CDIM];
__device__ float g_gbias[3072];

// weight plane offsets in __half elements
#define O_W00 0ull
#define O_W01 8388608ull
#define O_W10 25165824ull
#define O_W11 33554432ull
#define O_G0  50331648ull
#define O_OW  75497472ull

// ---------------- helpers ----------------
__device__ __forceinline__ uint32_t smem_u32(const void* p) {
    return (uint32_t)__cvta_generic_to_shared(p);
}
__device__ __forceinline__ void cpa16(uint32_t dst, const void* src) {
    asm volatile("cp.async.cg.shared.global [%0], [%1], 16;" :: "r"(dst), "l"(src));
}
__device__ __forceinline__ void ldm4(uint32_t* r, uint32_t a) {
    asm volatile("ldmatrix.sync.aligned.m8n8.x4.shared.b16 {%0,%1,%2,%3}, [%4];"
                 : "=r"(r[0]), "=r"(r[1]), "=r"(r[2]), "=r"(r[3]) : "r"(a));
}
__device__ __forceinline__ void ldmT4(uint32_t* r, uint32_t a) {
    asm volatile("ldmatrix.sync.aligned.m8n8.x4.trans.shared.b16 {%0,%1,%2,%3}, [%4];"
                 : "=r"(r[0]), "=r"(r[1]), "=r"(r[2]), "=r"(r[3]) : "r"(a));
}
__device__ __forceinline__ void mma_f16(float* d, const uint32_t* a, const uint32_t* b) {
    asm volatile("mma.sync.aligned.m16n8k16.row.col.f32.f16.f16.f32 "
                 "{%0,%1,%2,%3}, {%4,%5,%6,%7}, {%8,%9}, {%0,%1,%2,%3};"
                 : "+f"(d[0]), "+f"(d[1]), "+f"(d[2]), "+f"(d[3])
                 : "r"(a[0]), "r"(a[1]), "r"(a[2]), "r"(a[3]), "r"(b[0]), "r"(b[1]));
}
__device__ __forceinline__ uint32_t cvth(float x, float y) {
    __half2 h = __floats2half2_rn(x, y);
    return *reinterpret_cast<uint32_t*>(&h);
}
template <int ACT>
__device__ __forceinline__ float actf(float x, int col) {
    if (ACT == 1) return fmaxf(x, 0.0f);
    if (ACT == 4) return (col < 1024) ? tanhf(x) : 1.0f / (1.0f + expf(-x));
    return x;
}

// ---------------- 1-term GEMM: C[M,N] = act(fp16(A) @ fp16(B) + bias) ----------------
// A: fp16 plane [M,K]. B: fp16 plane [K,N]. SPLIT_OUT=1: fp16 out to Cs; else fp32 to Cf.
template <int ACT, int SPLIT_OUT>
__global__ void __launch_bounds__(256, 2)
hgemm(const __half* __restrict__ Ah,
      const __half* __restrict__ Bh,
      const float* __restrict__ bias,
      float* __restrict__ Cf, __half* __restrict__ Cs,
      int M, int N, int K, int tiles_m)
{
    extern __shared__ __align__(16) char smraw[];
    const uint32_t sb0 = smem_u32(smraw);

    const int t    = threadIdx.x;
    const int lane = t & 31;
    const int warp = t >> 5;
    const int wm   = warp >> 2;
    const int wn   = warp & 3;
    const int bm = (blockIdx.x % tiles_m) * 128;
    const int bn = (blockIdx.x / tiles_m) * 128;

    const int ar  = t >> 1;
    const int acH = (t & 1) * 16;
    const int br  = t >> 3;
    const int bcH = (t & 7) * 16;
    const __half* aS = Ah + (size_t)(bm + ar) * K + acH;
    const __half* bS = Bh + (size_t)br * N + bn + bcH;
    const uint32_t daB = (uint32_t)(ar * LDA + acH) * 2;
    const uint32_t dbB = (uint32_t)(br * LDB + bcH) * 2;

    float acc[4][4][4];
#pragma unroll
    for (int a = 0; a < 4; a++)
#pragma unroll
        for (int b = 0; b < 4; b++)
#pragma unroll
            for (int c = 0; c < 4; c++) acc[a][b][c] = 0.0f;

    const int nk = K / 32;

#define ISSUE(s_)                                                       \
    do {                                                                \
        const int s__ = (s_);                                           \
        if (s__ < nk) {                                                 \
            const uint32_t st = sb0 + (uint32_t)(s__ & 1) * STG;        \
            const __half* pa = aS + s__ * 32;                           \
            const uint32_t da = st + daB;                               \
            cpa16(da, pa);            cpa16(da + 16, pa + 8);           \
            const __half* pb = bS + (size_t)(s__ * 32) * N;             \
            const uint32_t db = st + APB + dbB;                         \
            cpa16(db, pb);            cpa16(db + 16, pb + 8);           \
        }                                                               \
        asm volatile("cp.async.commit_group;" ::: "memory");            \
    } while (0)

    ISSUE(0); ISSUE(1);

    for (int it = 0; it < nk; ++it) {
        asm volatile("cp.async.wait_group 1;" ::: "memory");
        __syncthreads();

        const uint32_t st  = sb0 + (uint32_t)(it & 1) * STG;
        const uint32_t aHi = st;
        const uint32_t bPl = st + APB;

#pragma unroll
        for (int ks = 0; ks < 2; ++ks) {
            uint32_t fB[4][2];
            const int krow  = ks * 16 + (lane & 15);
            const int nbase = wn * 32 + ((lane >> 4) << 3);
#pragma unroll
            for (int g = 0; g < 2; ++g) {
                const uint32_t off = (uint32_t)(krow * LDB + nbase + g * 16) * 2;
                uint32_t r[4];
                ldmT4(r, bPl + off);
                fB[2 * g][0] = r[0]; fB[2 * g][1] = r[1];
                fB[2 * g + 1][0] = r[2]; fB[2 * g + 1][1] = r[3];
            }
#pragma unroll
            for (int mt = 0; mt < 4; ++mt) {
                uint32_t fH[4];
                const uint32_t aoff =
                    (uint32_t)((wm * 64 + mt * 16 + (lane & 15)) * LDA +
                               ks * 16 + ((lane >> 4) << 3)) * 2;
                ldm4(fH, aHi + aoff);
#pragma unroll
                for (int nt = 0; nt < 4; ++nt) mma_f16(acc[mt][nt], fH, fB[nt]);
            }
        }
        __syncthreads();
        ISSUE(it + 2);
    }
#undef ISSUE

    // ---- epilogue
    const int rr = lane >> 2;
    const int cc = (lane & 3) * 2;
    if (SPLIT_OUT) {
        uint32_t* Chi = (uint32_t*)Cs;
#pragma unroll
        for (int mt = 0; mt < 4; ++mt) {
            const int row = bm + wm * 64 + mt * 16 + rr;
#pragma unroll
            for (int nt = 0; nt < 4; ++nt) {
                const int col = bn + wn * 32 + nt * 8 + cc;
                const float b0 = __ldg(bias + col);
                const float b1 = __ldg(bias + col + 1);
                Chi[((size_t)row * N + col) >> 1] =
                    cvth(actf<ACT>(acc[mt][nt][0] + b0, col),
                         actf<ACT>(acc[mt][nt][1] + b1, col));
                Chi[((size_t)(row + 8) * N + col) >> 1] =
                    cvth(actf<ACT>(acc[mt][nt][2] + b0, col),
                         actf<ACT>(acc[mt][nt][3] + b1, col));
            }
        }
    } else {
#pragma unroll
        for (int mt = 0; mt < 4; ++mt) {
            const int row = bm + wm * 64 + mt * 16 + rr;
#pragma unroll
            for (int nt = 0; nt < 4; ++nt) {
                const int col = bn + wn * 32 + nt * 8 + cc;
                const float b0 = __ldg(bias + col);
                const float b1 = __ldg(bias + col + 1);
                float2 o0, o1;
                o0.x = actf<ACT>(acc[mt][nt][0] + b0, col);
                o0.y = actf<ACT>(acc[mt][nt][1] + b1, col);
                o1.x = actf<ACT>(acc[mt][nt][2] + b0, col);
                o1.y = actf<ACT>(acc[mt][nt][3] + b1, col);
                *(float2*)(Cf + (size_t)row * N + col)       = o0;
                *(float2*)(Cf + (size_t)(row + 8) * N + col) = o1;
            }
        }
    }
}

// ---------------- weight convert fp32 -> fp16 plane ----------------
__device__ __forceinline__ void conv_one(
    long long i,
    const float* w00, const float* w01, const float* w10, const float* w11,
    const float* dw0, const float* fw0, const float* iw0,
    const float* ow, __half* wbuf)
{
    const float* s; long long jsrc; long long dsti = i;
    if (i < 4194304LL)        { s = w00; jsrc = i; }
    else if (i < 12582912LL)  { s = w01; jsrc = i - 4194304; }
    else if (i < 16777216LL)  { s = w10; jsrc = i - 12582912; }
    else if (i < 25165824LL)  { s = w11; jsrc = i - 16777216; }
    else if (i < 31457280LL) {
        const long long j = i - 25165824;
        const long long r = j / 1536, c2 = j % 1536;
        const int sel = (int)(c2 / 512);
        s = sel == 0 ? dw0 : (sel == 1 ? fw0 : iw0);
        jsrc = r * 512 + (c2 - (long long)sel * 512);
    }
    else { s = ow; jsrc = i - 31457280; dsti = i + 6291456; }  // skip unused G1 slot

    const float2 v = ((const float2*)s)[jsrc];
    ((uint32_t*)wbuf)[dsti] = cvth(v.x, v.y);
}

__global__ void __launch_bounds__(256)
wconv_range(const float* w00, const float* w01, const float* w10, const float* w11,
            const float* dw0, const float* fw0, const float* iw0,
            const float* ow, __half* wbuf, long long base, long long count)
{
    const long long i = base + (long long)blockIdx.x * 256 + threadIdx.x;
    if (i >= base + count || i >= 96993280LL) return;
    conv_one(i, w00, w01, w10, w11, dw0, fw0, iw0, ow, wbuf);
}

__global__ void __launch_bounds__(256)
gbias_kernel(const float* __restrict__ db, const float* __restrict__ fb,
             const float* __restrict__ ib, float* __restrict__ out)
{
    const int c = blockIdx.x * 256 + threadIdx.x;
    if (c >= 3072) return;
    out[c] = (c < 1024) ? db[c] : (c < 2048 ? fb[c - 1024] : ib[c - 2048]);
}

// ---------------- ctx half of concat -> fp16 plane (x half pre-filled by embed) ----------------
__global__ void __launch_bounds__(256)
concat_ctx_kernel(const float* __restrict__ ctx, __half* __restrict__ xcs, int first)
{
    const int gid = blockIdx.x * 256 + threadIdx.x;   // float4 over [4096,1024]
    const int row = gid >> 8;
    const int c4  = gid & 255;
    float4 v = first ? make_float4(0.f, 0.f, 0.f, 0.f)
                     : ((const float4*)ctx)[(size_t)row * 256 + c4];
    uint2* hi = (uint2*)xcs;
    hi[(size_t)row * 512 + 256 + c4] = make_uint2(cvth(v.x, v.y), cvth(v.z, v.w));
}

// ---------------- block reduction ----------------
__device__ __forceinline__ float block_sum(float v, float* sbuf) {
    const int lane = threadIdx.x & 31;
    const int wid  = threadIdx.x >> 5;
#pragma unroll
    for (int o = 16; o; o >>= 1) v += __shfl_xor_sync(0xffffffffu, v, o);
    if (lane == 0) sbuf[wid] = v;
    __syncthreads();
    if (threadIdx.x < 32) {
        float r = (threadIdx.x < 8) ? sbuf[threadIdx.x] : 0.0f;
#pragma unroll
        for (int o = 4; o; o >>= 1) r += __shfl_xor_sync(0xffffffffu, r, o);
        if (threadIdx.x == 0) sbuf[8] = r;
    }
    __syncthreads();
    return sbuf[8];
}

// ---------------- embed + LN -> x-half fp16 plane of xcs ----------------
__global__ void __launch_bounds__(256)
embed_ln_kernel(const int* __restrict__ ids, const float* __restrict__ table,
                const float* __restrict__ g, const float* __restrict__ b,
                __half* __restrict__ xcs)
{
    __shared__ float sbuf[16];
    const int row = blockIdx.x;
    const int t = threadIdx.x;          // thread t handles cols 4t..4t+3
    const float4 v = ((const float4*)(table + (size_t)ids[row] * EDIM))[t];
    float s  = v.x + v.y + v.z + v.w;
    float s2 = v.x * v.x + v.y * v.y + v.z * v.z + v.w * v.w;
    const float S  = block_sum(s, sbuf);
    const float S2 = block_sum(s2, sbuf);
    const float mean = S * (1.0f / EDIM);
    const float var  = S2 * (1.0f / EDIM) - mean * mean;
    const float rs   = rsqrtf(var + LN_EPS);
    const int c0 = 4 * t;
    float4 o;
    o.x = (v.x - mean) * rs * g[c0]     + b[c0];
    o.y = (v.y - mean) * rs * g[c0 + 1] + b[c0 + 1];
    o.z = (v.z - mean) * rs * g[c0 + 2] + b[c0 + 2];
    o.w = (v.w - mean) * rs * g[c0 + 3] + b[c0 + 3];
    uint2* hi = (uint2*)xcs;
    hi[(size_t)row * 512 + t] = make_uint2(cvth(o.x, o.y), cvth(o.z, o.w));
}

// gates layout: [delta | f | i] per row of 3072
__global__ void __launch_bounds__(256)
gate_ln_kernel(const float* __restrict__ gates, float* __restrict__ ctx,
               const float* __restrict__ g, const float* __restrict__ b, int first)
{
    __shared__ float sbuf[16];
    const int row = blockIdx.x;
    const int t = threadIdx.x;
    const float* gr = gates + (size_t)row * 3072;
    float v[4];
    float s = 0.0f, s2 = 0.0f;
#pragma unroll
    for (int j = 0; j < 4; j++) {
        const int c = t + j * 256;
        const float cv = first ? 0.0f : ctx[(size_t)row * CDIM + c];
        v[j] = gr[1024 + c] * cv + gr[2048 + c] * gr[c];
        s += v[j]; s2 += v[j] * v[j];
    }
    const float S  = block_sum(s, sbuf);
    const float S2 = block_sum(s2, sbuf);
    const float mean = S * (1.0f / CDIM);
    const float var  = S2 * (1.0f / CDIM) - mean * mean;
    const float rs   = rsqrtf(var + LN_EPS);
#pragma unroll
    for (int j = 0; j < 4; j++) {
        const int c = t + j * 256;
        ctx[(size_t)row * CDIM + c] = (v[j] - mean) * rs * g[c] + b[c];
    }
}

// ---------------- host dispatch ----------------
// mode 3: trunk relu, fp16 out | mode 1: gates tanh/sigm, fp32 out | mode 2: logits, fp32 out
static void run_gemm(int mode, const __half* Ah, const __half* Bh,
                     const float* bias, float* Cf, __half* Cs,
                     int M, int N, int K)
{
    const int tiles_m = M / 128;
    dim3 grid(tiles_m * (N / 128)), block(256);
    if (mode == 3) {
        cudaFuncSetAttribute(hgemm<1, 1>, cudaFuncAttributeMaxDynamicSharedMemorySize, GEMM_SMEM);
        hgemm<1, 1><<<grid, block, GEMM_SMEM>>>(Ah, Bh, bias, Cf, Cs, M, N, K, tiles_m);
    } else if (mode == 1) {
        cudaFuncSetAttribute(hgemm<4, 0>, cudaFuncAttributeMaxDynamicSharedMemorySize, GEMM_SMEM);
        hgemm<4, 0><<<grid, block, GEMM_SMEM>>>(Ah, Bh, bias, Cf, Cs, M, N, K, tiles_m);
    } else {
        cudaFuncSetAttribute(hgemm<0, 0>, cudaFuncAttributeMaxDynamicSharedMemorySize, GEMM_SMEM);
        hgemm<0, 0><<<grid, block, GEMM_SMEM>>>(Ah, Bh, bias, Cf, Cs, M, N, K, tiles_m);
    }
}

extern "C" void kernel_launch(void* const* d_in, const int* in_sizes, int n_in,
                              void* d_out, int out_size)
{
    const int*   ids   = (const int*)d_in[0];
    const float* table = (const float*)d_in[1];
    const float* en_g  = (const float*)d_in[2];
    const float* en_b  = (const float*)d_in[3];
    const float* bA[2] = {(const float*)d_in[5],  (const float*)d_in[9]};
    const float* bB[2] = {(const float*)d_in[7],  (const float*)d_in[11]};
    const float* cg0   = (const float*)d_in[18];
    const float* cb0   = (const float*)d_in[19];
    const float* ob    = (const float*)d_in[29];
    float* out = (float*)d_out;

    __half *wbuf, *xcs, *h1s, *hs;
    float *gate, *ctx, *gbias;
    cudaGetSymbolAddress((void**)&wbuf,  g_wbuf);
    cudaGetSymbolAddress((void**)&xcs,   g_xcs);
    cudaGetSymbolAddress((void**)&h1s,   g_h1s);
    cudaGetSymbolAddress((void**)&hs,    g_hs);
    cudaGetSymbolAddress((void**)&gate,  g_gate);
    cudaGetSymbolAddress((void**)&ctx,   g_ctx);
    cudaGetSymbolAddress((void**)&gbias, g_gbias);

    const float* W[8] = {
        (const float*)d_in[4],  (const float*)d_in[6],
        (const float*)d_in[8],  (const float*)d_in[10],
        (const float*)d_in[12], (const float*)d_in[14], (const float*)d_in[16],
        (const float*)d_in[28]};

    // 0: embed(+x-half plane), 1: concat_ctx(blk0 zeros), 2: conv w00,
    // 3: trunk GEMM 1 (profiled), 4: conv rest, ...
    embed_ln_kernel<<<NTOK, 256>>>(ids, table, en_g, en_b, xcs);
    concat_ctx_kernel<<<(NTOK * 1024 / 4) / 256, 256>>>(ctx, xcs, 1);
    wconv_range<<<(4194304 + 255) / 256, 256>>>(
        W[0], W[1], W[2], W[3], W[4], W[5], W[6], W[7],
        wbuf, 0LL, 4194304LL);
    run_gemm(3, xcs, wbuf + O_W00, bA[0], nullptr, h1s, NTOK, HDIM, EDIM + CDIM);
    wconv_range<<<(int)((96993280LL - 4194304LL + 255) / 256), 256>>>(
        W[0], W[1], W[2], W[3], W[4], W[5], W[6], W[7],
        wbuf, 4194304LL, 96993280LL - 4194304LL);
    run_gemm(3, h1s, wbuf + O_W01, bB[0], nullptr, hs, NTOK, HDIM, HDIM);
    gbias_kernel<<<12, 256>>>((const float*)d_in[13], (const float*)d_in[15],
                              (const float*)d_in[17], gbias);
    run_gemm(1, hs, wbuf + O_G0, gbias, gate, nullptr, NTOK, 3072, HDIM);
    gate_ln_kernel<<<NTOK, 256>>>(gate, ctx, cg0, cb0, 1);

    // block 1 trunk (block-1 gates remain dead code: final ctx never read)
    concat_ctx_kernel<<<(NTOK * 1024 / 4) / 256, 256>>>(ctx, xcs, 0);
    run_gemm(3, xcs, wbuf + O_W10, bA[1], nullptr, h1s, NTOK, HDIM, EDIM + CDIM);
    run_gemm(3, h1s, wbuf + O_W11, bB[1], nullptr, hs,  NTOK, HDIM, HDIM);

    // logits
    run_gemm(2, hs, wbuf + O_OW, ob, out, nullptr, NTOK, VDIM, HDIM);
}